// round 7
// baseline (speedup 1.0000x reference)
#include <cuda_runtime.h>
#include <math.h>

#define NB 512
#define NI 128
#define NH 256
#define NO 64
#define NT 512
#define RPB 4
#define NBLK (NB/RPB)

// ---------------- device scratch (no allocs allowed) ----------------
__device__ float g_Wt_i1[NI*NH];
__device__ float g_Wt_h1[NH*NH];
__device__ float g_Wt_i2[NH*NH];
__device__ float g_Wt_h2[NH*NH];
__device__ float g_Wt_i3[NH*NH];
__device__ float g_m1T[NT*NH];
__device__ float g_m2T[NT*NH];
__device__ float g_m3T[NT*NH];
__device__ float g_xT[(size_t)NB*NT*NI];   // [B][T][I]

// ---------------- XLA-CPU exp emulation (classic Cephes, GenerateVF32Exp) ----
__device__ __forceinline__ float xla_expf(float input){
    float xc = fminf(input, 88.3762626647950f);
    xc = fmaxf(xc, -88.3762626647949f);
    float fx = floorf(fmaf(xc, 1.44269504088896341f, 0.5f));
    float tmp = __fmul_rn(fx, 0.693359375f);
    float z   = __fmul_rn(fx, -2.12194440e-4f);
    float x   = __fsub_rn(xc, tmp);
    x = __fsub_rn(x, z);
    z = __fmul_rn(x, x);
    float y = fmaf(1.9875691500E-4f, x, 1.3981999507E-3f);
    y = fmaf(y, x, 8.3334519073E-3f);
    y = fmaf(y, x, 4.1665795894E-2f);
    y = fmaf(y, x, 1.6666665459E-1f);
    y = fmaf(y, x, 5.0000001201E-1f);
    y = fmaf(y, z, x);
    y = __fadd_rn(y, 1.0f);
    return ldexpf(y, (int)fx);   // exact 2^fx scaling
}

// ---------------- prep kernels ----------------
// transpose: dst[c*R + r] = src[r*C + c]
__global__ void tw_kernel(float* __restrict__ dst, const float* __restrict__ src, int R, int C){
    int idx = blockIdx.x*blockDim.x + threadIdx.x;
    if (idx < R*C){
        int r = idx / C, c = idx % C;
        dst[c*R + r] = src[idx];
    }
}

// x[B][I][T] -> g_xT[B][T][I]
__global__ void tx_kernel(const float* __restrict__ x){
    __shared__ float tile[32][33];
    int b  = blockIdx.z;
    int t0 = blockIdx.x*32, i0 = blockIdx.y*32;
    int tx = threadIdx.x, ty = threadIdx.y;
    const float* xb = x   + (size_t)b*NI*NT;
    float*       xo = g_xT + (size_t)b*NT*NI;
#pragma unroll
    for (int rr = ty; rr < 32; rr += 8)
        tile[rr][tx] = xb[(i0+rr)*NT + t0 + tx];
    __syncthreads();
#pragma unroll
    for (int rr = ty; rr < 32; rr += 8)
        xo[(size_t)(t0+rr)*NI + i0 + tx] = tile[tx][rr];
}

// ---------------- main recurrent kernel ----------------
// sequential ascending-j gather; fadd == fmaf(1,w,acc) bitwise, so this
// exactly reproduces Eigen's fused ascending-k fma chain over binary spikes
__device__ __forceinline__ float sparse_acc(const float* __restrict__ wb, const unsigned* words){
    float a = 0.f;
#pragma unroll
    for (int w = 0; w < 8; ++w){
        unsigned bits = words[w];
        const float* p = wb + (w*32)*NH;
        while (bits){
            int k = __ffs((int)bits) - 1; bits &= bits - 1;
            a = __fadd_rn(a, __ldg(p + k*NH));
        }
    }
    return a;
}

// cell update: plain RN ops, association exactly as the Python expression
__device__ __forceinline__ void cell_up(float inp, float mt, float alpha, float ro, float omro,
                                        float& mem, float& spk, float& bb){
    bb = __fadd_rn(__fmul_rn(ro, bb), __fmul_rn(omro, spk));
    float Bth = __fadd_rn(0.01f, __fmul_rn(1.8f, bb));
    float mem_new = __fsub_rn(__fadd_rn(__fmul_rn(mem, alpha), inp), __fmul_rn(Bth, spk));
    if (mt != 0.f) mem = mem_new;
    spk = (__fsub_rn(mem, Bth) > 0.f) ? mt : 0.f;
}

extern "C" __global__ void __launch_bounds__(512, 1)
rnn_kernel(const float* __restrict__ h1i, const float* __restrict__ h2i, const float* __restrict__ h3i,
           const float* __restrict__ bi1, const float* __restrict__ bh1,
           const float* __restrict__ bi2, const float* __restrict__ bh2,
           const float* __restrict__ bi3,
           const float* __restrict__ Wo,  const float* __restrict__ bo,
           const float* __restrict__ ta1, const float* __restrict__ ta2, const float* __restrict__ ta3,
           const float* __restrict__ tm1, const float* __restrict__ tm2, const float* __restrict__ tm3,
           float* __restrict__ out)
{
    __shared__ __align__(16) float xs[RPB][NI];
    __shared__ float s1f[RPB][NH];   // t==0 continuous spike operands
    __shared__ float s2f[RPB][NH];
    __shared__ unsigned s1w[RPB][8], s2w[RPB][8], s3w[RPB][8];

    const int tid  = threadIdx.x;
    const int h    = tid & (NH-1);
    const int g    = tid >> 8;
    const int lane = tid & 31;
    const int w8   = (tid >> 5) & 7;
    const int rA   = 2*g, rB = rA + 1;
    const int b0   = blockIdx.x * RPB;

    // parameters: exact XLA-CPU arithmetic (RN divide + emulated exp)
    const float alpha1 = xla_expf(__fdiv_rn(-1.f, tm1[h]));
    const float alpha2 = xla_expf(__fdiv_rn(-1.f, tm2[h]));
    const float alpha3 = xla_expf(__fdiv_rn(-1.f, tm3[h]));
    const float ro1 = xla_expf(__fdiv_rn(-1.f, ta1[h])), om1 = __fsub_rn(1.f, ro1);
    const float ro2 = xla_expf(__fdiv_rn(-1.f, ta2[h])), om2 = __fsub_rn(1.f, ro2);
    const float ro3 = xla_expf(__fdiv_rn(-1.f, ta3[h])), om3 = __fsub_rn(1.f, ro3);
    const float bias1 = __fadd_rn(bi1[h], bh1[h]);  // exact zeros in practice
    const float bias2 = __fadd_rn(bi2[h], bh2[h]);
    const float bias3 = bi3[h];

    float mem1A = h1i[(b0+rA)*NH + h], mem1B = h1i[(b0+rB)*NH + h];
    float spk1A = mem1A, spk1B = mem1B;     // carry0: spk init = h_init (continuous)
    float b1A = 0.01f, b1B = 0.01f;
    float mem2A = h2i[(b0+rA)*NH + h], mem2B = h2i[(b0+rB)*NH + h];
    float spk2A = mem2A, spk2B = mem2B;
    float b2A = 0.01f, b2B = 0.01f;
    float mem3A = h3i[(b0+rA)*NH + h], mem3B = h3i[(b0+rB)*NH + h];
    float spk3A = mem3A, spk3B = mem3B;
    float b3A = 0.01f, b3B = 0.01f;

    s1f[rA][h] = spk1A; s1f[rB][h] = spk1B;
    s2f[rA][h] = spk2A; s2f[rB][h] = spk2B;

    const float* wi1 = g_Wt_i1 + h;
    const float* wh1 = g_Wt_h1 + h;
    const float* wi2 = g_Wt_i2 + h;
    const float* wh2 = g_Wt_h2 + h;
    const float* wi3 = g_Wt_i3 + h;

    __syncthreads();

    for (int t = 0; t < NT; ++t){
        { int r = tid >> 7, i = tid & (NI-1);
          xs[r][i] = g_xT[((size_t)(b0+r)*NT + t)*NI + i]; }
        __syncthreads();

        const float m1t = g_m1T[t*NH + h];
        const float m2t = g_m2T[t*NH + h];
        const float m3t = g_m3T[t*NH + h];

        // ---- layer 1: h1 = (x@Wi1^T + b_i1 + s1@Wh1^T) + b_h1 ----
        // Eigen gemm: fused fma, single accumulator, ascending k from 0
        float dxA = 0.f, dxB = 0.f;
#pragma unroll 8
        for (int i = 0; i < NI; ++i){
            float w = __ldg(wi1 + i*NH);
            dxA = fmaf(xs[rA][i], w, dxA);
            dxB = fmaf(xs[rB][i], w, dxB);
        }
        float dsA, dsB;
        if (t == 0){
            dsA = 0.f; dsB = 0.f;
            for (int j = 0; j < NH; ++j){
                float w = __ldg(wh1 + j*NH);
                dsA = fmaf(s1f[rA][j], w, dsA);
                dsB = fmaf(s1f[rB][j], w, dsB);
            }
        } else {
            dsA = sparse_acc(wh1, s1w[rA]);
            dsB = sparse_acc(wh1, s1w[rB]);
        }
        float aA = __fadd_rn(__fadd_rn(dxA, dsA), bias1);
        float aB = __fadd_rn(__fadd_rn(dxB, dsB), bias1);
        __syncthreads();                        // reads of old s1w done

        cell_up(aA, m1t, alpha1, ro1, om1, mem1A, spk1A, b1A);
        cell_up(aB, m1t, alpha1, ro1, om1, mem1B, spk1B, b1B);
        { unsigned ba = __ballot_sync(0xffffffffu, spk1A != 0.f);
          unsigned bc = __ballot_sync(0xffffffffu, spk1B != 0.f);
          if (lane == 0){ s1w[rA][w8] = ba; s1w[rB][w8] = bc; } }
        __syncthreads();                        // new s1w visible

        // ---- layer 2: h2 = (s1@Wi2^T + b_i2 + s2@Wh2^T) + b_h2 ----
        float e1A = sparse_acc(wi2, s1w[rA]);
        float e1B = sparse_acc(wi2, s1w[rB]);
        float e2A, e2B;
        if (t == 0){
            e2A = 0.f; e2B = 0.f;
            for (int j = 0; j < NH; ++j){
                float w = __ldg(wh2 + j*NH);
                e2A = fmaf(s2f[rA][j], w, e2A);
                e2B = fmaf(s2f[rB][j], w, e2B);
            }
        } else {
            e2A = sparse_acc(wh2, s2w[rA]);
            e2B = sparse_acc(wh2, s2w[rB]);
        }
        aA = __fadd_rn(__fadd_rn(e1A, e2A), bias2);
        aB = __fadd_rn(__fadd_rn(e1B, e2B), bias2);
        __syncthreads();                        // reads of old s2w done

        cell_up(aA, m2t, alpha2, ro2, om2, mem2A, spk2A, b2A);
        cell_up(aB, m2t, alpha2, ro2, om2, mem2B, spk2B, b2B);
        { unsigned ba = __ballot_sync(0xffffffffu, spk2A != 0.f);
          unsigned bc = __ballot_sync(0xffffffffu, spk2B != 0.f);
          if (lane == 0){ s2w[rA][w8] = ba; s2w[rB][w8] = bc; } }
        __syncthreads();                        // new s2w visible

        // ---- layer 3: h3 = s2@Wi3^T + b_i3 ----
        aA = __fadd_rn(sparse_acc(wi3, s2w[rA]), bias3);
        aB = __fadd_rn(sparse_acc(wi3, s2w[rB]), bias3);
        cell_up(aA, m3t, alpha3, ro3, om3, mem3A, spk3A, b3A);
        cell_up(aB, m3t, alpha3, ro3, om3, mem3B, spk3B, b3B);
        if (t == NT-1){
            unsigned ba = __ballot_sync(0xffffffffu, spk3A != 0.f);
            unsigned bc = __ballot_sync(0xffffffffu, spk3B != 0.f);
            if (lane == 0){ s3w[rA][w8] = ba; s3w[rB][w8] = bc; }
        }
    }
    __syncthreads();

    // readout: out[r][o] = sigmoid(s3 @ Wo^T + bo); trajectory matched, so
    // ulp-level differences here are absorbed by the tolerance
    if (tid < RPB*NO){
        int r = tid / NO, o = tid % NO;
        float z = 0.f;
        const float* wo = Wo + o*NH;
#pragma unroll
        for (int w = 0; w < 8; ++w){
            unsigned bits = s3w[r][w];
            while (bits){
                int k = __ffs((int)bits) - 1; bits &= bits - 1;
                z = __fadd_rn(z, __ldg(wo + w*32 + k));
            }
        }
        z = __fadd_rn(z, bo[o]);
        out[(b0+r)*NO + o] = 1.f/(1.f + xla_expf(-z));
    }
}

// ---------------- launcher ----------------
extern "C" void kernel_launch(void* const* d_in, const int* in_sizes, int n_in,
                              void* d_out, int out_size){
    const float* x   = (const float*)d_in[0];
    const float* h1  = (const float*)d_in[1];
    const float* h2  = (const float*)d_in[2];
    const float* h3  = (const float*)d_in[3];
    const float* Wi1 = (const float*)d_in[4];
    const float* bi1 = (const float*)d_in[5];
    const float* Wh1 = (const float*)d_in[6];
    const float* bh1 = (const float*)d_in[7];
    const float* Wi2 = (const float*)d_in[8];
    const float* bi2 = (const float*)d_in[9];
    const float* Wh2 = (const float*)d_in[10];
    const float* bh2 = (const float*)d_in[11];
    const float* Wi3 = (const float*)d_in[12];
    const float* bi3 = (const float*)d_in[13];
    const float* Wo  = (const float*)d_in[14];
    const float* bo  = (const float*)d_in[15];
    const float* ta1 = (const float*)d_in[16];
    const float* ta2 = (const float*)d_in[17];
    const float* ta3 = (const float*)d_in[18];
    const float* tm1 = (const float*)d_in[19];
    const float* tm2 = (const float*)d_in[20];
    const float* tm3 = (const float*)d_in[21];
    const float* m1  = (const float*)d_in[22];
    const float* m2  = (const float*)d_in[23];
    const float* m3  = (const float*)d_in[24];

    float *pWi1, *pWh1, *pWi2, *pWh2, *pWi3, *pM1, *pM2, *pM3;
    cudaGetSymbolAddress((void**)&pWi1, g_Wt_i1);
    cudaGetSymbolAddress((void**)&pWh1, g_Wt_h1);
    cudaGetSymbolAddress((void**)&pWi2, g_Wt_i2);
    cudaGetSymbolAddress((void**)&pWh2, g_Wt_h2);
    cudaGetSymbolAddress((void**)&pWi3, g_Wt_i3);
    cudaGetSymbolAddress((void**)&pM1,  g_m1T);
    cudaGetSymbolAddress((void**)&pM2,  g_m2T);
    cudaGetSymbolAddress((void**)&pM3,  g_m3T);

    // weight transposes: Wt[k][h] = W[h][k]
    tw_kernel<<<(NH*NI + 255)/256, 256>>>(pWi1, Wi1, NH, NI);
    tw_kernel<<<(NH*NH + 255)/256, 256>>>(pWh1, Wh1, NH, NH);
    tw_kernel<<<(NH*NH + 255)/256, 256>>>(pWi2, Wi2, NH, NH);
    tw_kernel<<<(NH*NH + 255)/256, 256>>>(pWh2, Wh2, NH, NH);
    tw_kernel<<<(NH*NH + 255)/256, 256>>>(pWi3, Wi3, NH, NH);
    // mask transposes
    tw_kernel<<<(NH*NT + 255)/256, 256>>>(pM1, m1, NH, NT);
    tw_kernel<<<(NH*NT + 255)/256, 256>>>(pM2, m2, NH, NT);
    tw_kernel<<<(NH*NT + 255)/256, 256>>>(pM3, m3, NH, NT);
    // x transpose [B,I,T] -> [B,T,I]
    tx_kernel<<<dim3(NT/32, NI/32, NB), dim3(32, 8)>>>(x);

    rnn_kernel<<<NBLK, 512>>>(h1, h2, h3, bi1, bh1, bi2, bh2, bi3, Wo, bo,
                              ta1, ta2, ta3, tm1, tm2, tm3, (float*)d_out);
}

// round 8
// speedup vs baseline: 3.3430x; 3.3430x over previous
#include <cuda_runtime.h>
#include <math.h>

#define NB 512
#define NI 128
#define NH 256
#define NO 64
#define NT 512
#define RPB 4
#define NBLK (NB/RPB)

// ---------------- device scratch (no allocs allowed) ----------------
__device__ float g_Wt_i1[NI*NH];
__device__ float g_Wt_h1[NH*NH];
__device__ float g_Wt_i2[NH*NH];
__device__ float g_Wt_h2[NH*NH];
__device__ float g_Wt_i3[NH*NH];
__device__ float g_m1T[NT*NH];
__device__ float g_m2T[NT*NH];
__device__ float g_m3T[NT*NH];
__device__ float g_xT[(size_t)NB*NT*NI];   // [B][T][I]

// ---------------- XLA-CPU exp emulation (classic Cephes, GenerateVF32Exp) ----
__device__ __forceinline__ float xla_expf(float input){
    float xc = fminf(input, 88.3762626647950f);
    xc = fmaxf(xc, -88.3762626647949f);
    float fx = floorf(fmaf(xc, 1.44269504088896341f, 0.5f));
    float tmp = __fmul_rn(fx, 0.693359375f);
    float z   = __fmul_rn(fx, -2.12194440e-4f);
    float x   = __fsub_rn(xc, tmp);
    x = __fsub_rn(x, z);
    z = __fmul_rn(x, x);
    float y = fmaf(1.9875691500E-4f, x, 1.3981999507E-3f);
    y = fmaf(y, x, 8.3334519073E-3f);
    y = fmaf(y, x, 4.1665795894E-2f);
    y = fmaf(y, x, 1.6666665459E-1f);
    y = fmaf(y, x, 5.0000001201E-1f);
    y = fmaf(y, z, x);
    y = __fadd_rn(y, 1.0f);
    return ldexpf(y, (int)fx);   // exact 2^fx scaling
}

// ---------------- prep kernels ----------------
__global__ void tw_kernel(float* __restrict__ dst, const float* __restrict__ src, int R, int C){
    int idx = blockIdx.x*blockDim.x + threadIdx.x;
    if (idx < R*C){
        int r = idx / C, c = idx % C;
        dst[c*R + r] = src[idx];
    }
}

__global__ void tx_kernel(const float* __restrict__ x){
    __shared__ float tile[32][33];
    int b  = blockIdx.z;
    int t0 = blockIdx.x*32, i0 = blockIdx.y*32;
    int tx = threadIdx.x, ty = threadIdx.y;
    const float* xb = x   + (size_t)b*NI*NT;
    float*       xo = g_xT + (size_t)b*NT*NI;
#pragma unroll
    for (int rr = ty; rr < 32; rr += 8)
        tile[rr][tx] = xb[(i0+rr)*NT + t0 + tx];
    __syncthreads();
#pragma unroll
    for (int rr = ty; rr < 32; rr += 8)
        xo[(size_t)(t0+rr)*NI + i0 + tx] = tile[tx][rr];
}

// ---------------- batched list gather ----------------
// adds strictly ascending over idx[] (ascending j) == bitwise-identical to the
// reference's fused ascending-k chain over binary spikes. Loads are batched 16
// deep for MLP; tail lanes add +0.0f which is value-exact.
__device__ __forceinline__ float list_acc(const float* __restrict__ wb,
                                          const unsigned short* __restrict__ idx,
                                          int cnt){
    float a = 0.f;
    for (int i = 0; i < cnt; i += 16){
        float v[16];
#pragma unroll
        for (int u = 0; u < 16; ++u){
            int j = i + u;
            v[u] = (j < cnt) ? __ldg(wb + (int)idx[j]*NH) : 0.f;
        }
#pragma unroll
        for (int u = 0; u < 16; ++u)
            a = __fadd_rn(a, v[u]);
    }
    return a;
}

// cell update: plain RN ops, association exactly as the Python expression
__device__ __forceinline__ void cell_up(float inp, float mt, float alpha, float ro, float omro,
                                        float& mem, float& spk, float& bb){
    bb = __fadd_rn(__fmul_rn(ro, bb), __fmul_rn(omro, spk));
    float Bth = __fadd_rn(0.01f, __fmul_rn(1.8f, bb));
    float mem_new = __fsub_rn(__fadd_rn(__fmul_rn(mem, alpha), inp), __fmul_rn(Bth, spk));
    if (mt != 0.f) mem = mem_new;
    spk = (__fsub_rn(mem, Bth) > 0.f) ? mt : 0.f;
}

extern "C" __global__ void __launch_bounds__(512, 1)
rnn_kernel(const float* __restrict__ h1i, const float* __restrict__ h2i, const float* __restrict__ h3i,
           const float* __restrict__ bi1, const float* __restrict__ bh1,
           const float* __restrict__ bi2, const float* __restrict__ bh2,
           const float* __restrict__ bi3,
           const float* __restrict__ Wo,  const float* __restrict__ bo,
           const float* __restrict__ ta1, const float* __restrict__ ta2, const float* __restrict__ ta3,
           const float* __restrict__ tm1, const float* __restrict__ tm2, const float* __restrict__ tm3,
           float* __restrict__ out)
{
    __shared__ __align__(16) float xs[RPB][NI];
    __shared__ float s1f[RPB][NH];   // t==0 continuous spike operands
    __shared__ float s2f[RPB][NH];
    __shared__ unsigned s1w[RPB][8], s2w[RPB][8], s3w[RPB][8];
    __shared__ unsigned short s1idx[RPB][NH], s2idx[RPB][NH];
    __shared__ int s1cnt[RPB], s2cnt[RPB];

    const int tid  = threadIdx.x;
    const int h    = tid & (NH-1);
    const int g    = tid >> 8;
    const int lane = tid & 31;
    const int w8   = (tid >> 5) & 7;
    const unsigned lmlt = (1u << lane) - 1u;
    const int rA   = 2*g, rB = rA + 1;
    const int b0   = blockIdx.x * RPB;

    // parameters: exact XLA-CPU arithmetic (RN divide + emulated exp)
    const float alpha1 = xla_expf(__fdiv_rn(-1.f, tm1[h]));
    const float alpha2 = xla_expf(__fdiv_rn(-1.f, tm2[h]));
    const float alpha3 = xla_expf(__fdiv_rn(-1.f, tm3[h]));
    const float ro1 = xla_expf(__fdiv_rn(-1.f, ta1[h])), om1 = __fsub_rn(1.f, ro1);
    const float ro2 = xla_expf(__fdiv_rn(-1.f, ta2[h])), om2 = __fsub_rn(1.f, ro2);
    const float ro3 = xla_expf(__fdiv_rn(-1.f, ta3[h])), om3 = __fsub_rn(1.f, ro3);
    const float bias1 = __fadd_rn(bi1[h], bh1[h]);
    const float bias2 = __fadd_rn(bi2[h], bh2[h]);
    const float bias3 = bi3[h];

    float mem1A = h1i[(b0+rA)*NH + h], mem1B = h1i[(b0+rB)*NH + h];
    float spk1A = mem1A, spk1B = mem1B;     // carry0: spk init = h_init (continuous)
    float b1A = 0.01f, b1B = 0.01f;
    float mem2A = h2i[(b0+rA)*NH + h], mem2B = h2i[(b0+rB)*NH + h];
    float spk2A = mem2A, spk2B = mem2B;
    float b2A = 0.01f, b2B = 0.01f;
    float mem3A = h3i[(b0+rA)*NH + h], mem3B = h3i[(b0+rB)*NH + h];
    float spk3A = mem3A, spk3B = mem3B;
    float b3A = 0.01f, b3B = 0.01f;

    s1f[rA][h] = spk1A; s1f[rB][h] = spk1B;
    s2f[rA][h] = spk2A; s2f[rB][h] = spk2B;

    const float* wi1 = g_Wt_i1 + h;
    const float* wh1 = g_Wt_h1 + h;
    const float* wi2 = g_Wt_i2 + h;
    const float* wh2 = g_Wt_h2 + h;
    const float* wi3 = g_Wt_i3 + h;

    __syncthreads();

    for (int t = 0; t < NT; ++t){
        { int r = tid >> 7, i = tid & (NI-1);
          xs[r][i] = g_xT[((size_t)(b0+r)*NT + t)*NI + i]; }
        __syncthreads();

        const float m1t = g_m1T[t*NH + h];
        const float m2t = g_m2T[t*NH + h];
        const float m3t = g_m3T[t*NH + h];

        // ---- layer 1: h1 = (x@Wi1^T + b_i1 + s1@Wh1^T) + b_h1 ----
        float dxA = 0.f, dxB = 0.f;
#pragma unroll 8
        for (int i = 0; i < NI; ++i){
            float w = __ldg(wi1 + i*NH);
            dxA = fmaf(xs[rA][i], w, dxA);
            dxB = fmaf(xs[rB][i], w, dxB);
        }
        float dsA, dsB;
        if (t == 0){
            dsA = 0.f; dsB = 0.f;
            for (int j = 0; j < NH; ++j){
                float w = __ldg(wh1 + j*NH);
                dsA = fmaf(s1f[rA][j], w, dsA);
                dsB = fmaf(s1f[rB][j], w, dsB);
            }
        } else {
            dsA = list_acc(wh1, s1idx[rA], s1cnt[rA]);
            dsB = list_acc(wh1, s1idx[rB], s1cnt[rB]);
        }
        float aA = __fadd_rn(__fadd_rn(dxA, dsA), bias1);
        float aB = __fadd_rn(__fadd_rn(dxB, dsB), bias1);
        __syncthreads();                        // reads of old s1 list done

        cell_up(aA, m1t, alpha1, ro1, om1, mem1A, spk1A, b1A);
        cell_up(aB, m1t, alpha1, ro1, om1, mem1B, spk1B, b1B);
        { unsigned ba = __ballot_sync(0xffffffffu, spk1A != 0.f);
          unsigned bc = __ballot_sync(0xffffffffu, spk1B != 0.f);
          if (lane == 0){ s1w[rA][w8] = ba; s1w[rB][w8] = bc; } }
        __syncthreads();                        // s1w visible

        // build ascending index lists for s1 (rows rA, rB)
        {
            unsigned mywA = s1w[rA][w8], mywB = s1w[rB][w8];
            int befA = 0, befB = 0;
#pragma unroll
            for (int w = 0; w < 7; ++w){
                if (w < w8){ befA += __popc(s1w[rA][w]); befB += __popc(s1w[rB][w]); }
            }
            if (spk1A != 0.f) s1idx[rA][befA + __popc(mywA & lmlt)] = (unsigned short)h;
            if (spk1B != 0.f) s1idx[rB][befB + __popc(mywB & lmlt)] = (unsigned short)h;
            if (h == NH-1){
                s1cnt[rA] = befA + __popc(mywA);
                s1cnt[rB] = befB + __popc(mywB);
            }
        }
        __syncthreads();                        // new s1 list visible

        // ---- layer 2: h2 = (s1@Wi2^T + b_i2 + s2@Wh2^T) + b_h2 ----
        float e1A = list_acc(wi2, s1idx[rA], s1cnt[rA]);
        float e1B = list_acc(wi2, s1idx[rB], s1cnt[rB]);
        float e2A, e2B;
        if (t == 0){
            e2A = 0.f; e2B = 0.f;
            for (int j = 0; j < NH; ++j){
                float w = __ldg(wh2 + j*NH);
                e2A = fmaf(s2f[rA][j], w, e2A);
                e2B = fmaf(s2f[rB][j], w, e2B);
            }
        } else {
            e2A = list_acc(wh2, s2idx[rA], s2cnt[rA]);
            e2B = list_acc(wh2, s2idx[rB], s2cnt[rB]);
        }
        aA = __fadd_rn(__fadd_rn(e1A, e2A), bias2);
        aB = __fadd_rn(__fadd_rn(e1B, e2B), bias2);
        __syncthreads();                        // reads of old s2 list done

        cell_up(aA, m2t, alpha2, ro2, om2, mem2A, spk2A, b2A);
        cell_up(aB, m2t, alpha2, ro2, om2, mem2B, spk2B, b2B);
        { unsigned ba = __ballot_sync(0xffffffffu, spk2A != 0.f);
          unsigned bc = __ballot_sync(0xffffffffu, spk2B != 0.f);
          if (lane == 0){ s2w[rA][w8] = ba; s2w[rB][w8] = bc; } }
        __syncthreads();                        // s2w visible

        // build ascending index lists for s2 (rows rA, rB)
        {
            unsigned mywA = s2w[rA][w8], mywB = s2w[rB][w8];
            int befA = 0, befB = 0;
#pragma unroll
            for (int w = 0; w < 7; ++w){
                if (w < w8){ befA += __popc(s2w[rA][w]); befB += __popc(s2w[rB][w]); }
            }
            if (spk2A != 0.f) s2idx[rA][befA + __popc(mywA & lmlt)] = (unsigned short)h;
            if (spk2B != 0.f) s2idx[rB][befB + __popc(mywB & lmlt)] = (unsigned short)h;
            if (h == NH-1){
                s2cnt[rA] = befA + __popc(mywA);
                s2cnt[rB] = befB + __popc(mywB);
            }
        }
        __syncthreads();                        // new s2 list visible

        // ---- layer 3: h3 = s2@Wi3^T + b_i3 ----
        aA = __fadd_rn(list_acc(wi3, s2idx[rA], s2cnt[rA]), bias3);
        aB = __fadd_rn(list_acc(wi3, s2idx[rB], s2cnt[rB]), bias3);
        cell_up(aA, m3t, alpha3, ro3, om3, mem3A, spk3A, b3A);
        cell_up(aB, m3t, alpha3, ro3, om3, mem3B, spk3B, b3B);
        if (t == NT-1){
            unsigned ba = __ballot_sync(0xffffffffu, spk3A != 0.f);
            unsigned bc = __ballot_sync(0xffffffffu, spk3B != 0.f);
            if (lane == 0){ s3w[rA][w8] = ba; s3w[rB][w8] = bc; }
        }
    }
    __syncthreads();

    // readout: out[r][o] = sigmoid(s3 @ Wo^T + bo)
    if (tid < RPB*NO){
        int r = tid / NO, o = tid % NO;
        float z = 0.f;
        const float* wo = Wo + o*NH;
#pragma unroll
        for (int w = 0; w < 8; ++w){
            unsigned bits = s3w[r][w];
            while (bits){
                int k = __ffs((int)bits) - 1; bits &= bits - 1;
                z = __fadd_rn(z, __ldg(wo + w*32 + k));
            }
        }
        z = __fadd_rn(z, bo[o]);
        out[(b0+r)*NO + o] = 1.f/(1.f + xla_expf(-z));
    }
}

// ---------------- launcher ----------------
extern "C" void kernel_launch(void* const* d_in, const int* in_sizes, int n_in,
                              void* d_out, int out_size){
    const float* x   = (const float*)d_in[0];
    const float* h1  = (const float*)d_in[1];
    const float* h2  = (const float*)d_in[2];
    const float* h3  = (const float*)d_in[3];
    const float* Wi1 = (const float*)d_in[4];
    const float* bi1 = (const float*)d_in[5];
    const float* Wh1 = (const float*)d_in[6];
    const float* bh1 = (const float*)d_in[7];
    const float* Wi2 = (const float*)d_in[8];
    const float* bi2 = (const float*)d_in[9];
    const float* Wh2 = (const float*)d_in[10];
    const float* bh2 = (const float*)d_in[11];
    const float* Wi3 = (const float*)d_in[12];
    const float* bi3 = (const float*)d_in[13];
    const float* Wo  = (const float*)d_in[14];
    const float* bo  = (const float*)d_in[15];
    const float* ta1 = (const float*)d_in[16];
    const float* ta2 = (const float*)d_in[17];
    const float* ta3 = (const float*)d_in[18];
    const float* tm1 = (const float*)d_in[19];
    const float* tm2 = (const float*)d_in[20];
    const float* tm3 = (const float*)d_in[21];
    const float* m1  = (const float*)d_in[22];
    const float* m2  = (const float*)d_in[23];
    const float* m3  = (const float*)d_in[24];

    float *pWi1, *pWh1, *pWi2, *pWh2, *pWi3, *pM1, *pM2, *pM3;
    cudaGetSymbolAddress((void**)&pWi1, g_Wt_i1);
    cudaGetSymbolAddress((void**)&pWh1, g_Wt_h1);
    cudaGetSymbolAddress((void**)&pWi2, g_Wt_i2);
    cudaGetSymbolAddress((void**)&pWh2, g_Wt_h2);
    cudaGetSymbolAddress((void**)&pWi3, g_Wt_i3);
    cudaGetSymbolAddress((void**)&pM1,  g_m1T);
    cudaGetSymbolAddress((void**)&pM2,  g_m2T);
    cudaGetSymbolAddress((void**)&pM3,  g_m3T);

    tw_kernel<<<(NH*NI + 255)/256, 256>>>(pWi1, Wi1, NH, NI);
    tw_kernel<<<(NH*NH + 255)/256, 256>>>(pWh1, Wh1, NH, NH);
    tw_kernel<<<(NH*NH + 255)/256, 256>>>(pWi2, Wi2, NH, NH);
    tw_kernel<<<(NH*NH + 255)/256, 256>>>(pWh2, Wh2, NH, NH);
    tw_kernel<<<(NH*NH + 255)/256, 256>>>(pWi3, Wi3, NH, NH);
    tw_kernel<<<(NH*NT + 255)/256, 256>>>(pM1, m1, NH, NT);
    tw_kernel<<<(NH*NT + 255)/256, 256>>>(pM2, m2, NH, NT);
    tw_kernel<<<(NH*NT + 255)/256, 256>>>(pM3, m3, NH, NT);
    tx_kernel<<<dim3(NT/32, NI/32, NB), dim3(32, 8)>>>(x);

    rnn_kernel<<<NBLK, 512>>>(h1, h2, h3, bi1, bh1, bi2, bh2, bi3, Wo, bo,
                              ta1, ta2, ta3, tm1, tm2, tm3, (float*)d_out);
}

// round 9
// speedup vs baseline: 3.3629x; 1.0059x over previous
#include <cuda_runtime.h>
#include <math.h>

#define NB 512
#define NI 128
#define NH 256
#define NO 64
#define NT 512
#define RPB 4
#define NBLK (NB/RPB)

// ---------------- device scratch (no allocs allowed) ----------------
__device__ float g_Wt_i1[NI*NH];
__device__ float g_Wt_h1[NH*NH];
__device__ float g_Wt_i2[NH*NH];
__device__ float g_Wt_h2[NH*NH];
__device__ float g_Wt_i3[NH*NH];
__device__ float g_m1T[NT*NH];
__device__ float g_m2T[NT*NH];
__device__ float g_m3T[NT*NH];
__device__ float g_xT[(size_t)NB*NT*NI];   // [B][T][I]

// ---------------- XLA-CPU exp emulation (classic Cephes, GenerateVF32Exp) ----
__device__ __forceinline__ float xla_expf(float input){
    float xc = fminf(input, 88.3762626647950f);
    xc = fmaxf(xc, -88.3762626647949f);
    float fx = floorf(fmaf(xc, 1.44269504088896341f, 0.5f));
    float tmp = __fmul_rn(fx, 0.693359375f);
    float z   = __fmul_rn(fx, -2.12194440e-4f);
    float x   = __fsub_rn(xc, tmp);
    x = __fsub_rn(x, z);
    z = __fmul_rn(x, x);
    float y = fmaf(1.9875691500E-4f, x, 1.3981999507E-3f);
    y = fmaf(y, x, 8.3334519073E-3f);
    y = fmaf(y, x, 4.1665795894E-2f);
    y = fmaf(y, x, 1.6666665459E-1f);
    y = fmaf(y, x, 5.0000001201E-1f);
    y = fmaf(y, z, x);
    y = __fadd_rn(y, 1.0f);
    return ldexpf(y, (int)fx);   // exact 2^fx scaling
}

// ---------------- prep kernels ----------------
__global__ void tw_kernel(float* __restrict__ dst, const float* __restrict__ src, int R, int C){
    int idx = blockIdx.x*blockDim.x + threadIdx.x;
    if (idx < R*C){
        int r = idx / C, c = idx % C;
        dst[c*R + r] = src[idx];
    }
}

__global__ void tx_kernel(const float* __restrict__ x){
    __shared__ float tile[32][33];
    int b  = blockIdx.z;
    int t0 = blockIdx.x*32, i0 = blockIdx.y*32;
    int tx = threadIdx.x, ty = threadIdx.y;
    const float* xb = x   + (size_t)b*NI*NT;
    float*       xo = g_xT + (size_t)b*NT*NI;
#pragma unroll
    for (int rr = ty; rr < 32; rr += 8)
        tile[rr][tx] = xb[(i0+rr)*NT + t0 + tx];
    __syncthreads();
#pragma unroll
    for (int rr = ty; rr < 32; rr += 8)
        xo[(size_t)(t0+rr)*NI + i0 + tx] = tile[tx][rr];
}

// ---------------- batched list gather ----------------
// adds strictly ascending over idx[] (ascending j) == bitwise-identical to the
// reference's fused ascending-k chain over binary spikes. Loads are batched 16
// deep for MLP; tail lanes add +0.0f which is value-exact.
__device__ __forceinline__ float list_acc(const float* __restrict__ wb,
                                          const unsigned short* __restrict__ idx,
                                          int cnt){
    float a = 0.f;
    for (int i = 0; i < cnt; i += 16){
        float v[16];
#pragma unroll
        for (int u = 0; u < 16; ++u){
            int j = i + u;
            v[u] = (j < cnt) ? __ldg(wb + (int)idx[j]*NH) : 0.f;
        }
#pragma unroll
        for (int u = 0; u < 16; ++u)
            a = __fadd_rn(a, v[u]);
    }
    return a;
}

// cell update: plain RN ops, association exactly as the Python expression
__device__ __forceinline__ void cell_up(float inp, float mt, float alpha, float ro, float omro,
                                        float& mem, float& spk, float& bb){
    bb = __fadd_rn(__fmul_rn(ro, bb), __fmul_rn(omro, spk));
    float Bth = __fadd_rn(0.01f, __fmul_rn(1.8f, bb));
    float mem_new = __fsub_rn(__fadd_rn(__fmul_rn(mem, alpha), inp), __fmul_rn(Bth, spk));
    if (mt != 0.f) mem = mem_new;
    spk = (__fsub_rn(mem, Bth) > 0.f) ? mt : 0.f;
}

extern "C" __global__ void __launch_bounds__(512, 1)
rnn_kernel(const float* __restrict__ h1i, const float* __restrict__ h2i, const float* __restrict__ h3i,
           const float* __restrict__ bi1, const float* __restrict__ bh1,
           const float* __restrict__ bi2, const float* __restrict__ bh2,
           const float* __restrict__ bi3,
           const float* __restrict__ Wo,  const float* __restrict__ bo,
           const float* __restrict__ ta1, const float* __restrict__ ta2, const float* __restrict__ ta3,
           const float* __restrict__ tm1, const float* __restrict__ tm2, const float* __restrict__ tm3,
           float* __restrict__ out)
{
    __shared__ __align__(16) float xs[RPB][NI];
    __shared__ float s1f[RPB][NH];   // t==0 continuous spike operands
    __shared__ float s2f[RPB][NH];
    __shared__ unsigned s1w[RPB][8], s2w[RPB][8], s3w[RPB][8];
    __shared__ unsigned short s1idx[RPB][NH], s2idx[RPB][NH];
    __shared__ int s1cnt[RPB], s2cnt[RPB];

    const int tid  = threadIdx.x;
    const int h    = tid & (NH-1);
    const int g    = tid >> 8;
    const int lane = tid & 31;
    const int w8   = (tid >> 5) & 7;
    const unsigned lmlt = (1u << lane) - 1u;
    const int rA   = 2*g, rB = rA + 1;
    const int b0   = blockIdx.x * RPB;

    // parameters: exact XLA-CPU arithmetic (RN divide + emulated exp)
    const float alpha1 = xla_expf(__fdiv_rn(-1.f, tm1[h]));
    const float alpha2 = xla_expf(__fdiv_rn(-1.f, tm2[h]));
    const float alpha3 = xla_expf(__fdiv_rn(-1.f, tm3[h]));
    const float ro1 = xla_expf(__fdiv_rn(-1.f, ta1[h])), om1 = __fsub_rn(1.f, ro1);
    const float ro2 = xla_expf(__fdiv_rn(-1.f, ta2[h])), om2 = __fsub_rn(1.f, ro2);
    const float ro3 = xla_expf(__fdiv_rn(-1.f, ta3[h])), om3 = __fsub_rn(1.f, ro3);
    const float bias1 = __fadd_rn(bi1[h], bh1[h]);
    const float bias2 = __fadd_rn(bi2[h], bh2[h]);
    const float bias3 = bi3[h];

    float mem1A = h1i[(b0+rA)*NH + h], mem1B = h1i[(b0+rB)*NH + h];
    float spk1A = mem1A, spk1B = mem1B;     // carry0: spk init = h_init (continuous)
    float b1A = 0.01f, b1B = 0.01f;
    float mem2A = h2i[(b0+rA)*NH + h], mem2B = h2i[(b0+rB)*NH + h];
    float spk2A = mem2A, spk2B = mem2B;
    float b2A = 0.01f, b2B = 0.01f;
    float mem3A = h3i[(b0+rA)*NH + h], mem3B = h3i[(b0+rB)*NH + h];
    float spk3A = mem3A, spk3B = mem3B;
    float b3A = 0.01f, b3B = 0.01f;

    s1f[rA][h] = spk1A; s1f[rB][h] = spk1B;
    s2f[rA][h] = spk2A; s2f[rB][h] = spk2B;

    const float* wi1 = g_Wt_i1 + h;
    const float* wh1 = g_Wt_h1 + h;
    const float* wi2 = g_Wt_i2 + h;
    const float* wh2 = g_Wt_h2 + h;
    const float* wi3 = g_Wt_i3 + h;

    __syncthreads();

    for (int t = 0; t < NT; ++t){
        { int r = tid >> 7, i = tid & (NI-1);
          xs[r][i] = g_xT[((size_t)(b0+r)*NT + t)*NI + i]; }
        __syncthreads();

        const float m1t = g_m1T[t*NH + h];
        const float m2t = g_m2T[t*NH + h];
        const float m3t = g_m3T[t*NH + h];

        // ---- layer 1: h1 = (x@Wi1^T + b_i1 + s1@Wh1^T) + b_h1 ----
        float dxA = 0.f, dxB = 0.f;
#pragma unroll 8
        for (int i = 0; i < NI; ++i){
            float w = __ldg(wi1 + i*NH);
            dxA = fmaf(xs[rA][i], w, dxA);
            dxB = fmaf(xs[rB][i], w, dxB);
        }
        float dsA, dsB;
        if (t == 0){
            dsA = 0.f; dsB = 0.f;
            for (int j = 0; j < NH; ++j){
                float w = __ldg(wh1 + j*NH);
                dsA = fmaf(s1f[rA][j], w, dsA);
                dsB = fmaf(s1f[rB][j], w, dsB);
            }
        } else {
            dsA = list_acc(wh1, s1idx[rA], s1cnt[rA]);
            dsB = list_acc(wh1, s1idx[rB], s1cnt[rB]);
        }
        float aA = __fadd_rn(__fadd_rn(dxA, dsA), bias1);
        float aB = __fadd_rn(__fadd_rn(dxB, dsB), bias1);
        __syncthreads();                        // reads of old s1 list done

        cell_up(aA, m1t, alpha1, ro1, om1, mem1A, spk1A, b1A);
        cell_up(aB, m1t, alpha1, ro1, om1, mem1B, spk1B, b1B);
        { unsigned ba = __ballot_sync(0xffffffffu, spk1A != 0.f);
          unsigned bc = __ballot_sync(0xffffffffu, spk1B != 0.f);
          if (lane == 0){ s1w[rA][w8] = ba; s1w[rB][w8] = bc; } }
        __syncthreads();                        // s1w visible

        // build ascending index lists for s1 (rows rA, rB)
        {
            unsigned mywA = s1w[rA][w8], mywB = s1w[rB][w8];
            int befA = 0, befB = 0;
#pragma unroll
            for (int w = 0; w < 7; ++w){
                if (w < w8){ befA += __popc(s1w[rA][w]); befB += __popc(s1w[rB][w]); }
            }
            if (spk1A != 0.f) s1idx[rA][befA + __popc(mywA & lmlt)] = (unsigned short)h;
            if (spk1B != 0.f) s1idx[rB][befB + __popc(mywB & lmlt)] = (unsigned short)h;
            if (h == NH-1){
                s1cnt[rA] = befA + __popc(mywA);
                s1cnt[rB] = befB + __popc(mywB);
            }
        }
        __syncthreads();                        // new s1 list visible

        // ---- layer 2: h2 = (s1@Wi2^T + b_i2 + s2@Wh2^T) + b_h2 ----
        float e1A = list_acc(wi2, s1idx[rA], s1cnt[rA]);
        float e1B = list_acc(wi2, s1idx[rB], s1cnt[rB]);
        float e2A, e2B;
        if (t == 0){
            e2A = 0.f; e2B = 0.f;
            for (int j = 0; j < NH; ++j){
                float w = __ldg(wh2 + j*NH);
                e2A = fmaf(s2f[rA][j], w, e2A);
                e2B = fmaf(s2f[rB][j], w, e2B);
            }
        } else {
            e2A = list_acc(wh2, s2idx[rA], s2cnt[rA]);
            e2B = list_acc(wh2, s2idx[rB], s2cnt[rB]);
        }
        aA = __fadd_rn(__fadd_rn(e1A, e2A), bias2);
        aB = __fadd_rn(__fadd_rn(e1B, e2B), bias2);
        __syncthreads();                        // reads of old s2 list done

        cell_up(aA, m2t, alpha2, ro2, om2, mem2A, spk2A, b2A);
        cell_up(aB, m2t, alpha2, ro2, om2, mem2B, spk2B, b2B);
        { unsigned ba = __ballot_sync(0xffffffffu, spk2A != 0.f);
          unsigned bc = __ballot_sync(0xffffffffu, spk2B != 0.f);
          if (lane == 0){ s2w[rA][w8] = ba; s2w[rB][w8] = bc; } }
        __syncthreads();                        // s2w visible

        // build ascending index lists for s2 (rows rA, rB)
        {
            unsigned mywA = s2w[rA][w8], mywB = s2w[rB][w8];
            int befA = 0, befB = 0;
#pragma unroll
            for (int w = 0; w < 7; ++w){
                if (w < w8){ befA += __popc(s2w[rA][w]); befB += __popc(s2w[rB][w]); }
            }
            if (spk2A != 0.f) s2idx[rA][befA + __popc(mywA & lmlt)] = (unsigned short)h;
            if (spk2B != 0.f) s2idx[rB][befB + __popc(mywB & lmlt)] = (unsigned short)h;
            if (h == NH-1){
                s2cnt[rA] = befA + __popc(mywA);
                s2cnt[rB] = befB + __popc(mywB);
            }
        }
        __syncthreads();                        // new s2 list visible

        // ---- layer 3: h3 = s2@Wi3^T + b_i3 ----
        aA = __fadd_rn(list_acc(wi3, s2idx[rA], s2cnt[rA]), bias3);
        aB = __fadd_rn(list_acc(wi3, s2idx[rB], s2cnt[rB]), bias3);
        cell_up(aA, m3t, alpha3, ro3, om3, mem3A, spk3A, b3A);
        cell_up(aB, m3t, alpha3, ro3, om3, mem3B, spk3B, b3B);
        if (t == NT-1){
            unsigned ba = __ballot_sync(0xffffffffu, spk3A != 0.f);
            unsigned bc = __ballot_sync(0xffffffffu, spk3B != 0.f);
            if (lane == 0){ s3w[rA][w8] = ba; s3w[rB][w8] = bc; }
        }
    }
    __syncthreads();

    // readout: out[r][o] = sigmoid(s3 @ Wo^T + bo)
    if (tid < RPB*NO){
        int r = tid / NO, o = tid % NO;
        float z = 0.f;
        const float* wo = Wo + o*NH;
#pragma unroll
        for (int w = 0; w < 8; ++w){
            unsigned bits = s3w[r][w];
            while (bits){
                int k = __ffs((int)bits) - 1; bits &= bits - 1;
                z = __fadd_rn(z, __ldg(wo + w*32 + k));
            }
        }
        z = __fadd_rn(z, bo[o]);
        out[(b0+r)*NO + o] = 1.f/(1.f + xla_expf(-z));
    }
}

// ---------------- launcher ----------------
extern "C" void kernel_launch(void* const* d_in, const int* in_sizes, int n_in,
                              void* d_out, int out_size){
    const float* x   = (const float*)d_in[0];
    const float* h1  = (const float*)d_in[1];
    const float* h2  = (const float*)d_in[2];
    const float* h3  = (const float*)d_in[3];
    const float* Wi1 = (const float*)d_in[4];
    const float* bi1 = (const float*)d_in[5];
    const float* Wh1 = (const float*)d_in[6];
    const float* bh1 = (const float*)d_in[7];
    const float* Wi2 = (const float*)d_in[8];
    const float* bi2 = (const float*)d_in[9];
    const float* Wh2 = (const float*)d_in[10];
    const float* bh2 = (const float*)d_in[11];
    const float* Wi3 = (const float*)d_in[12];
    const float* bi3 = (const float*)d_in[13];
    const float* Wo  = (const float*)d_in[14];
    const float* bo  = (const float*)d_in[15];
    const float* ta1 = (const float*)d_in[16];
    const float* ta2 = (const float*)d_in[17];
    const float* ta3 = (const float*)d_in[18];
    const float* tm1 = (const float*)d_in[19];
    const float* tm2 = (const float*)d_in[20];
    const float* tm3 = (const float*)d_in[21];
    const float* m1  = (const float*)d_in[22];
    const float* m2  = (const float*)d_in[23];
    const float* m3  = (const float*)d_in[24];

    float *pWi1, *pWh1, *pWi2, *pWh2, *pWi3, *pM1, *pM2, *pM3;
    cudaGetSymbolAddress((void**)&pWi1, g_Wt_i1);
    cudaGetSymbolAddress((void**)&pWh1, g_Wt_h1);
    cudaGetSymbolAddress((void**)&pWi2, g_Wt_i2);
    cudaGetSymbolAddress((void**)&pWh2, g_Wt_h2);
    cudaGetSymbolAddress((void**)&pWi3, g_Wt_i3);
    cudaGetSymbolAddress((void**)&pM1,  g_m1T);
    cudaGetSymbolAddress((void**)&pM2,  g_m2T);
    cudaGetSymbolAddress((void**)&pM3,  g_m3T);

    tw_kernel<<<(NH*NI + 255)/256, 256>>>(pWi1, Wi1, NH, NI);
    tw_kernel<<<(NH*NH + 255)/256, 256>>>(pWh1, Wh1, NH, NH);
    tw_kernel<<<(NH*NH + 255)/256, 256>>>(pWi2, Wi2, NH, NH);
    tw_kernel<<<(NH*NH + 255)/256, 256>>>(pWh2, Wh2, NH, NH);
    tw_kernel<<<(NH*NH + 255)/256, 256>>>(pWi3, Wi3, NH, NH);
    tw_kernel<<<(NH*NT + 255)/256, 256>>>(pM1, m1, NH, NT);
    tw_kernel<<<(NH*NT + 255)/256, 256>>>(pM2, m2, NH, NT);
    tw_kernel<<<(NH*NT + 255)/256, 256>>>(pM3, m3, NH, NT);
    tx_kernel<<<dim3(NT/32, NI/32, NB), dim3(32, 8)>>>(x);

    rnn_kernel<<<NBLK, 512>>>(h1, h2, h3, bi1, bh1, bi2, bh2, bi3, Wo, bo,
                              ta1, ta2, ta3, tm1, tm2, tm3, (float*)d_out);
}